// round 1
// baseline (speedup 1.0000x reference)
#include <cuda_runtime.h>
#include <cstdint>

// 3-level db4 wavedec (periodization) along axis 1 of (64, 4096, 64) fp32.
// Output rows: [cA3 (512) | cD3 (512) | cD2 (1024) | cD1 (2048)] x 64 feats.
//
// One block = one batch x one tile of T3=16 level-3 outputs (=> 32 cD2,
// 64 cD1 rows). Full F=64 width per block for perfect coalescing.

#define T3       16
#define FEAT     64
#define NTHREADS 512

#define X_ROWS   170   // 8*T3 + 42 (input window incl. halo)
#define A1_ROWS  82    // 4*T3 + 18
#define A2_ROWS  38    // 2*T3 + 6

// padded capacities (rows) so 4-wide compute never reads/writes out of smem
#define X_CAP    184
#define A1_CAP   96
#define A2_CAP   48

#define SMEM_FLOATS ((X_CAP + A1_CAP + A2_CAP) * FEAT)
#define SMEM_BYTES  (SMEM_FLOATS * 4)

// Reversed db4 filters: out[i] = sum_t src[2i + t] * R*[t]
// RLO[t] = DEC_LO[7-t]; RHI[t] = DEC_HI[7-t] = DEC_LO[t] * (t even ? +1 : -1)
__device__ __forceinline__ void dwt4(const float* __restrict__ src, int i0, int f,
                                     float a[4], float d[4]) {
    const float RLO[8] = {
         0.23037781330885523f,  0.7148465705525415f,   0.6308807679295904f,
        -0.02798376941698385f, -0.18703481171888114f,  0.030841381835986965f,
         0.032883011666982945f, -0.010597401784997278f };
    const float RHI[8] = {
        -0.010597401784997278f, -0.032883011666982945f, 0.030841381835986965f,
         0.18703481171888114f,  -0.02798376941698385f, -0.6308807679295904f,
         0.7148465705525415f,   -0.23037781330885523f };

    float v[14];
#pragma unroll
    for (int t = 0; t < 14; ++t)
        v[t] = src[(2 * i0 + t) * FEAT + f];

#pragma unroll
    for (int q = 0; q < 4; ++q) {
        float av = 0.f, dv = 0.f;
#pragma unroll
        for (int t = 0; t < 8; ++t) {
            av = fmaf(v[2 * q + t], RLO[t], av);
            dv = fmaf(v[2 * q + t], RHI[t], dv);
        }
        a[q] = av;
        d[q] = dv;
    }
}

__global__ void __launch_bounds__(NTHREADS, 2)
wavedec_kernel(const float* __restrict__ x, float* __restrict__ out) {
    extern __shared__ float s[];
    float* s_x  = s;
    float* s_a1 = s + X_CAP * FEAT;
    float* s_a2 = s_a1 + A1_CAP * FEAT;

    const int tid  = threadIdx.x;
    const int tile = blockIdx.x;   // 0..31
    const int b    = blockIdx.y;   // 0..63

    const float* __restrict__ xb = x   + (size_t)b * 4096 * FEAT;
    float*       __restrict__ ob = out + (size_t)b * 4096 * FEAT;

    // ---- Load x window: rows (128*tile - 42 + o) mod 4096, o in [0,170) ----
    {
        const int f4 = tid & 15;      // 16 float4 per row
        const int r0 = tid >> 4;      // 32 rows per pass
        const int g0 = 128 * tile - 42 + 4096;
#pragma unroll
        for (int pass = 0; pass < 6; ++pass) {
            int o = pass * 32 + r0;
            if (o < X_ROWS) {
                int gr = (g0 + o) & 4095;
                float4 v = *reinterpret_cast<const float4*>(xb + (size_t)gr * FEAT + f4 * 4);
                *reinterpret_cast<float4*>(s_x + o * FEAT + f4 * 4) = v;
            }
        }
    }
    __syncthreads();

    const int f  = tid & 63;
    const int rg = (tid >> 6) * 4;   // row group: 0,4,...,28 (32 rows/pass)

    // ---- Level 1: x(170) -> cA1(82 rows in smem), cD1[18..82) -> global ----
#pragma unroll
    for (int pass = 0; pass < 3; ++pass) {
        int i0 = pass * 32 + rg;
        if (i0 < A1_ROWS) {
            float a[4], d[4];
            dwt4(s_x, i0, f, a, d);
#pragma unroll
            for (int q = 0; q < 4; ++q) {
                int i = i0 + q;
                s_a1[i * FEAT + f] = a[q];
                if (i >= 18 && i < A1_ROWS)
                    ob[(size_t)(2048 + 64 * tile + (i - 18)) * FEAT + f] = d[q];
            }
        }
    }
    __syncthreads();

    // ---- Level 2: cA1(82) -> cA2(38 rows in smem), cD2[6..38) -> global ----
#pragma unroll
    for (int pass = 0; pass < 2; ++pass) {
        int i0 = pass * 32 + rg;
        if (i0 < A2_ROWS) {
            float a[4], d[4];
            dwt4(s_a1, i0, f, a, d);
#pragma unroll
            for (int q = 0; q < 4; ++q) {
                int i = i0 + q;
                s_a2[i * FEAT + f] = a[q];
                if (i >= 6 && i < A2_ROWS)
                    ob[(size_t)(1024 + 32 * tile + (i - 6)) * FEAT + f] = d[q];
            }
        }
    }
    __syncthreads();

    // ---- Level 3: cA2(38) -> cA3[0..16), cD3[0..16) -> global ----
    {
        int i0 = rg;
        if (i0 < T3) {
            float a[4], d[4];
            dwt4(s_a2, i0, f, a, d);
#pragma unroll
            for (int q = 0; q < 4; ++q) {
                int i = i0 + q;
                ob[(size_t)(16 * tile + i) * FEAT + f]       = a[q];
                ob[(size_t)(512 + 16 * tile + i) * FEAT + f] = d[q];
            }
        }
    }
}

extern "C" void kernel_launch(void* const* d_in, const int* in_sizes, int n_in,
                              void* d_out, int out_size) {
    const float* x = (const float*)d_in[0];
    float* out = (float*)d_out;

    cudaFuncSetAttribute(wavedec_kernel,
                         cudaFuncAttributeMaxDynamicSharedMemorySize, SMEM_BYTES);

    dim3 grid(32, 64);
    wavedec_kernel<<<grid, NTHREADS, SMEM_BYTES>>>(x, out);
}

// round 2
// speedup vs baseline: 1.1566x; 1.1566x over previous
#include <cuda_runtime.h>
#include <cstdint>

// 3-level db4 wavedec (periodization) along axis 1 of (64, 4096, 64) fp32.
// Output rows: [cA3 (512) | cD3 (512) | cD2 (1024) | cD1 (2048)] x 64 feats.
//
// R2: level-1 reads x directly from global (coalesced, no smem staging);
// all data paths are float2 per thread (2 features); only cA1/cA2 staged
// in (static) shared memory.

#define NTHREADS 512
#define A1_ROWS  82   // 4*16 + 18 valid local cA1 rows
#define A2_ROWS  38   // 2*16 + 6  valid local cA2 rows
#define A1_CAP   88   // level-2 reads up to row 85
#define A2_CAP   40   // level-3 reads up to row 37; writes up to 39

// Reversed db4 filters: out[i] = sum_t src[2i + t] * R*[t]
__device__ __forceinline__ void dwt_from_v(const float2 v[14], float2 a[4], float2 d[4]) {
    const float RLO[8] = {
         0.23037781330885523f,  0.7148465705525415f,   0.6308807679295904f,
        -0.02798376941698385f, -0.18703481171888114f,  0.030841381835986965f,
         0.032883011666982945f, -0.010597401784997278f };
    const float RHI[8] = {
        -0.010597401784997278f, -0.032883011666982945f, 0.030841381835986965f,
         0.18703481171888114f,  -0.02798376941698385f, -0.6308807679295904f,
         0.7148465705525415f,   -0.23037781330885523f };
#pragma unroll
    for (int q = 0; q < 4; ++q) {
        float2 av = make_float2(0.f, 0.f);
        float2 dv = make_float2(0.f, 0.f);
#pragma unroll
        for (int t = 0; t < 8; ++t) {
            const float2 w = v[2 * q + t];
            av.x = fmaf(w.x, RLO[t], av.x);
            av.y = fmaf(w.y, RLO[t], av.y);
            dv.x = fmaf(w.x, RHI[t], dv.x);
            dv.y = fmaf(w.y, RHI[t], dv.y);
        }
        a[q] = av;
        d[q] = dv;
    }
}

__global__ void __launch_bounds__(NTHREADS, 2)
wavedec_kernel(const float* __restrict__ x, float* __restrict__ out) {
    __shared__ float2 s_a1[A1_CAP * 32];
    __shared__ float2 s_a2[A2_CAP * 32];

    const int tid  = threadIdx.x;
    const int f2   = tid & 31;    // float2 feature lane (64 floats = 32 float2)
    const int grp  = tid >> 5;    // 0..15, each group handles 4 output rows
    const int tile = blockIdx.x;  // 0..31
    const int b    = blockIdx.y;  // 0..63

    const float2* __restrict__ xb2 =
        reinterpret_cast<const float2*>(x + (size_t)b * 4096 * 64);
    float2* __restrict__ ob2 =
        reinterpret_cast<float2*>(out + (size_t)b * 4096 * 64);

    const int g0 = 128 * tile - 42;  // global x row of local window origin

    // ---- Level 1: x (global) -> cA1 (smem) + cD1 (global) ----
#pragma unroll
    for (int pass = 0; pass < 2; ++pass) {
        const int i0 = pass * 64 + grp * 4;
        if (i0 < A1_ROWS) {
            float2 v[14];
            const int r0 = g0 + 2 * i0;
            if (r0 >= 0 && r0 <= 4096 - 14) {
                const float2* p = xb2 + (size_t)r0 * 32 + f2;
#pragma unroll
                for (int t = 0; t < 14; ++t)
                    v[t] = p[t * 32];
            } else {
#pragma unroll
                for (int t = 0; t < 14; ++t) {
                    const int r = (r0 + t + 4096) & 4095;
                    v[t] = xb2[(size_t)r * 32 + f2];
                }
            }
            float2 a[4], d[4];
            dwt_from_v(v, a, d);
#pragma unroll
            for (int q = 0; q < 4; ++q) {
                const int i = i0 + q;          // max 83 < A1_CAP
                s_a1[i * 32 + f2] = a[q];
                if (i >= 18 && i < A1_ROWS)
                    ob2[(size_t)(2048 + 64 * tile + (i - 18)) * 32 + f2] = d[q];
            }
        }
    }
    __syncthreads();

    // ---- Level 2: cA1 (smem) -> cA2 (smem) + cD2 (global) ----
    {
        const int i0 = grp * 4;
        if (i0 < A2_ROWS) {
            float2 v[14];
#pragma unroll
            for (int t = 0; t < 14; ++t)
                v[t] = s_a1[(2 * i0 + t) * 32 + f2];
            float2 a[4], d[4];
            dwt_from_v(v, a, d);
#pragma unroll
            for (int q = 0; q < 4; ++q) {
                const int i = i0 + q;          // max 39 < A2_CAP
                s_a2[i * 32 + f2] = a[q];
                if (i >= 6 && i < A2_ROWS)
                    ob2[(size_t)(1024 + 32 * tile + (i - 6)) * 32 + f2] = d[q];
            }
        }
    }
    __syncthreads();

    // ---- Level 3: cA2 (smem) -> cA3 + cD3 (global) ----
    {
        const int i0 = grp * 4;
        if (i0 < 16) {
            float2 v[14];
#pragma unroll
            for (int t = 0; t < 14; ++t)
                v[t] = s_a2[(2 * i0 + t) * 32 + f2];
            float2 a[4], d[4];
            dwt_from_v(v, a, d);
#pragma unroll
            for (int q = 0; q < 4; ++q) {
                const int i = i0 + q;
                ob2[(size_t)(16 * tile + i) * 32 + f2]         = a[q];
                ob2[(size_t)(512 + 16 * tile + i) * 32 + f2]   = d[q];
            }
        }
    }
}

extern "C" void kernel_launch(void* const* d_in, const int* in_sizes, int n_in,
                              void* d_out, int out_size) {
    const float* x = (const float*)d_in[0];
    float* out = (float*)d_out;
    dim3 grid(32, 64);
    wavedec_kernel<<<grid, NTHREADS>>>(x, out);
}